// round 3
// baseline (speedup 1.0000x reference)
#include <cuda_runtime.h>
#include <math.h>

// ---------------- problem constants ----------------
#define BB   128   // batch
#define TSEQ 128   // sequence length
#define DIN  128   // input dim
#define HID  512   // hidden
#define MWIN 32    // attention window
#define NG   5     // gates

// packed widths
#define NA   3584  // [W_sh(512) | Wh*5(2560) | Wah(512)]
#define NB   2560  // Ws*5
#define ND   512   // [W_h ; W_e] output width (K=1024)

// ---------------- workspace (single device global) ----------------
// float offsets
#define OFF_XS    0ull                                   // [B*T, 512]
#define SZ_XS     (16384ull*512ull)
#define OFF_XG    (OFF_XS + SZ_XS)                       // [B*T, 2560]
#define SZ_XG     (16384ull*2560ull)
#define OFF_GP    (OFF_XG + SZ_XG)                       // [B*T, 512]
#define SZ_GP     (16384ull*512ull)
#define OFF_WA    (OFF_GP + SZ_GP)                       // [512, 3584]
#define SZ_WA     (512ull*3584ull)
#define OFF_WB    (OFF_WA + SZ_WA)                       // [512, 2560]
#define SZ_WB     (512ull*2560ull)
#define OFF_WD    (OFF_WB + SZ_WB)                       // [1024, 512]
#define SZ_WD     (1024ull*512ull)
#define OFF_WXG   (OFF_WD + SZ_WD)                       // [128, 2560]
#define SZ_WXG    (128ull*2560ull)
#define OFF_PREA  (OFF_WXG + SZ_WXG)                     // [128, 2560] (gate part of GEMM A)
#define SZ_PREA   (128ull*2560ull)
#define OFF_PREB  (OFF_PREA + SZ_PREA)                   // [2][128,2560]
#define SZ_PREB   (2ull*128ull*2560ull)
#define OFF_QS    (OFF_PREB + SZ_PREB)                   // [8][128,512]
#define SZ_QS     (8ull*128ull*512ull)
#define OFF_HS    (OFF_QS + SZ_QS)                       // [8][128,512]
#define SZ_HS     (8ull*128ull*512ull)
#define OFF_S     (OFF_HS + SZ_HS)                       // [128,512]
#define SZ_S      (128ull*512ull)
#define OFF_H     (OFF_S + SZ_S)                         // [128,512]
#define SZ_H      (128ull*512ull)
#define OFF_C     (OFF_H + SZ_H)                         // [128,512]
#define SZ_C      (128ull*512ull)
#define OFF_HC    (OFF_C + SZ_C)                         // [128,1024]  [h_tilde | c]
#define SZ_HC     (128ull*1024ull)
#define OFF_HE    (OFF_HC + SZ_HC)                       // [128,1024]  [h_tilde | e]
#define SZ_HE     (128ull*1024ull)
#define OFF_BUF   (OFF_HE + SZ_HE)                       // [128,32,512] circular h history
#define SZ_BUF    (128ull*32ull*512ull)
#define OFF_P     (OFF_BUF + SZ_BUF)                     // [128,32,512] projected history
#define SZ_P      (128ull*32ull*512ull)
#define WS_TOTAL  (OFF_P + SZ_P)

__device__ float g_ws[WS_TOTAL];

// ---------------- fast transcendentals (abs err ~1e-7) ----------------
__device__ __forceinline__ float ftanh(float x) {
    float e = __expf(2.0f * x);
    return 1.0f - __fdividef(2.0f, e + 1.0f);
}
__device__ __forceinline__ float fsig(float x) {
    return __fdividef(1.0f, 1.0f + __expf(-x));
}

// ---------------- generic SIMT GEMM: C[128*gridDim.y, N] = A @ W ----------------
// Block tile: 128 x 32, BK = 16, 256 threads, 4x4 per thread.
// split-K via blockIdx.z (A += z*K cols, W += z*K rows, out += z*gridDim.y*128*ldo).
// EPI: 0 = raw store, 1 = +bias[n], 2 = +p3[m]*p2[n]+p1[n] (XS prologue),
//      3 = GEMM-A special (s=tanh(acc+XS_t), preA gate store, P-slot store)
#define GK 16
template<int EPI>
__global__ void __launch_bounds__(256) gemm_k(
    const float* __restrict__ A, int lda,
    const float* __restrict__ W, int ldw,
    int K,
    float* __restrict__ out, int ldo,
    const float* __restrict__ p1,
    const float* __restrict__ p2,
    const float* __restrict__ p3,
    float* __restrict__ q1,
    float* __restrict__ q2,
    float* __restrict__ q3)
{
    __shared__ float As[GK][128];
    __shared__ float Wsm[GK][32];

    const int tid = threadIdx.x;
    const int tx  = tid & 7;    // n quad
    const int ty  = tid >> 3;   // m quad
    const int n0  = blockIdx.x * 32;
    const int m0  = blockIdx.y * 128;
    const int z   = blockIdx.z;

    const float* Ab = A + (size_t)m0 * lda + (size_t)z * K;
    const float* Wb = W + (size_t)z * K * ldw + n0;

    float acc[4][4];
#pragma unroll
    for (int r = 0; r < 4; r++)
#pragma unroll
        for (int c = 0; c < 4; c++) acc[r][c] = 0.0f;

    const int ntile = K / GK;
    for (int kt = 0; kt < ntile; kt++) {
        // A tile: 128 x 16  (512 float4 loads)
#pragma unroll
        for (int it = 0; it < 2; it++) {
            int i  = tid + it * 256;
            int m  = i >> 2;
            int kq = (i & 3) << 2;
            float4 v = *reinterpret_cast<const float4*>(Ab + (size_t)m * lda + kt * GK + kq);
            As[kq + 0][m] = v.x; As[kq + 1][m] = v.y;
            As[kq + 2][m] = v.z; As[kq + 3][m] = v.w;
        }
        // W tile: 16 x 32 (128 float4 loads)
        if (tid < 128) {
            int k  = tid >> 3;
            int nq = (tid & 7) << 2;
            float4 v = *reinterpret_cast<const float4*>(Wb + (size_t)(kt * GK + k) * ldw + nq);
            *reinterpret_cast<float4*>(&Wsm[k][nq]) = v;
        }
        __syncthreads();
#pragma unroll
        for (int k = 0; k < GK; k++) {
            float4 av = *reinterpret_cast<const float4*>(&As[k][ty * 4]);
            float4 wv = *reinterpret_cast<const float4*>(&Wsm[k][tx * 4]);
            float aa[4] = {av.x, av.y, av.z, av.w};
            float ww[4] = {wv.x, wv.y, wv.z, wv.w};
#pragma unroll
            for (int r = 0; r < 4; r++)
#pragma unroll
                for (int c = 0; c < 4; c++)
                    acc[r][c] = fmaf(aa[r], ww[c], acc[r][c]);
        }
        __syncthreads();
    }

    // epilogue
    const size_t zoff = (size_t)z * gridDim.y * 128 * (EPI == 3 ? 0 : ldo);
#pragma unroll
    for (int r = 0; r < 4; r++) {
        int m = m0 + ty * 4 + r;
#pragma unroll
        for (int c = 0; c < 4; c++) {
            int n = n0 + tx * 4 + c;
            float v = acc[r][c];
            if (EPI == 0) {
                out[zoff + (size_t)m * ldo + n] = v;
            } else if (EPI == 1) {
                out[(size_t)m * ldo + n] = v + p1[n];
            } else if (EPI == 2) {
                out[(size_t)m * ldo + n] = v + p3[m] * p2[n] + p1[n];
            } else { // EPI == 3 : GEMM-A
                if (n0 < 512) {
                    // s = tanh(h@W_sh + XS_t)   (XS already holds x@W_sx + d*W_st + b_s)
                    q1[(size_t)m * 512 + n] = ftanh(v + p1[(size_t)m * (TSEQ * HID) + n]);
                } else if (n0 < 3072) {
                    q2[(size_t)m * 2560 + (n - 512)] = v;   // gate h-pre
                } else {
                    q3[(size_t)m * (MWIN * HID) + (n - 3072)] = v; // P[:,slot,:] = h_prev@Wah
                }
            }
        }
    }
}

// ---------------- pack kernels (run every replay, cheap) ----------------
__global__ void packA_k(const float* __restrict__ Wsh, const float* __restrict__ Wh,
                        const float* __restrict__ Wah)
{
    int idx = blockIdx.x * 256 + threadIdx.x;          // 512*3584
    int k = idx / NA, n = idx % NA;
    float v;
    if (n < 512) v = Wsh[k * 512 + n];
    else if (n < 3072) {
        int g = (n - 512) >> 9, h = (n - 512) & 511;
        v = Wh[(size_t)g * 262144 + k * 512 + h];
    } else v = Wah[k * 512 + (n - 3072)];
    g_ws[OFF_WA + idx] = v;
}
__global__ void packB_k(const float* __restrict__ Ws5)
{
    int idx = blockIdx.x * 256 + threadIdx.x;          // 512*2560
    int k = idx / NB, n = idx % NB;
    int g = n >> 9, h = n & 511;
    g_ws[OFF_WB + idx] = Ws5[(size_t)g * 262144 + k * 512 + h];
}
__global__ void packD_k(const float* __restrict__ W_h, const float* __restrict__ W_e)
{
    int idx = blockIdx.x * 256 + threadIdx.x;          // 1024*512
    int k = idx >> 9, n = idx & 511;
    g_ws[OFF_WD + idx] = (k < 512) ? W_h[k * 512 + n] : W_e[(k - 512) * 512 + n];
}
__global__ void packXG_k(const float* __restrict__ Wx5)
{
    int idx = blockIdx.x * 256 + threadIdx.x;          // 128*2560
    int d = idx / NB, n = idx % NB;
    int g = n >> 9, h = n & 511;
    g_ws[OFF_WXG + idx] = Wx5[(size_t)g * 65536 + d * 512 + h];
}
__global__ void zero_hc_k()
{
    int idx = blockIdx.x * 256 + threadIdx.x;          // 2*65536
    if (idx < 65536) g_ws[OFF_H + idx] = 0.0f;
    else             g_ws[OFF_C + (idx - 65536)] = 0.0f;
}

// ---------------- cell kernel ----------------
__global__ void __launch_bounds__(256) cell_k(const float* __restrict__ XG_t, int t)
{
    int idx = blockIdx.x * 256 + threadIdx.x;  // 0..65535
    int b = idx >> 9, h = idx & 511;
    const float* preA  = g_ws + OFF_PREA;
    const float* preB0 = g_ws + OFF_PREB;
    const float* preB1 = g_ws + OFF_PREB + 128ull * 2560ull;
    float pre[NG];
#pragma unroll
    for (int g = 0; g < NG; g++) {
        size_t col = (size_t)g * 512 + h;
        pre[g] = preA[(size_t)b * 2560 + col] + preB0[(size_t)b * 2560 + col]
               + preB1[(size_t)b * 2560 + col] + XG_t[(size_t)b * (TSEQ * 2560) + col];
    }
    float f  = fsig(pre[0]);
    float i_ = fsig(pre[1]);
    float Tt = fsig(pre[2]);
    float zt = ftanh(pre[3]);
    float o  = fsig(pre[4]);
    float sv = g_ws[OFF_S + idx];
    float cv = f * g_ws[OFF_C + idx] + i_ * zt + Tt * sv;
    g_ws[OFF_C + idx] = cv;
    float ht = o * ftanh(cv);
    g_ws[OFF_HC + (size_t)b * 1024 + h]       = ht;
    g_ws[OFF_HC + (size_t)b * 1024 + 512 + h] = cv;
    g_ws[OFF_HE + (size_t)b * 1024 + h]       = ht;
}

// ---------------- attention kernel (one block per batch row) ----------------
__global__ void __launch_bounds__(256) attn_k(
    const float* __restrict__ ba, const float* __restrict__ vt, int t)
{
    __shared__ float qv[512];
    __shared__ float sc[32];
    __shared__ float al[32];
    int b = blockIdx.x, tid = threadIdx.x;
    float* he = g_ws + OFF_HE;
    if (t == 0) {
        he[(size_t)b * 1024 + 512 + tid]       = 0.0f;
        he[(size_t)b * 1024 + 512 + 256 + tid] = 0.0f;
        return;
    }
    int nv = (t < MWIN) ? t : MWIN;
    const float* qs  = g_ws + OFF_QS;
    const float* P   = g_ws + OFF_P;
    const float* buf = g_ws + OFF_BUF;
#pragma unroll
    for (int j = 0; j < 2; j++) {
        int h = tid + j * 256;
        float q = ba[h];
#pragma unroll
        for (int s = 0; s < 8; s++) q += qs[(size_t)s * 65536 + (size_t)b * 512 + h];
        qv[h] = q;
    }
    __syncthreads();
    int wid = tid >> 5, lane = tid & 31;
    for (int mi = wid; mi < nv; mi += 8) {
        int slot = (t - 1 - mi) & 31;
        const float* Pp = P + ((size_t)b * 32 + slot) * 512;
        float ps = 0.0f;
        for (int h = lane; h < 512; h += 32)
            ps += vt[h] * ftanh(qv[h] + Pp[h]);
#pragma unroll
        for (int o = 16; o; o >>= 1) ps += __shfl_xor_sync(0xffffffffu, ps, o);
        if (lane == 0) sc[mi] = ps;
    }
    __syncthreads();
    if (wid == 0) {
        float s = (lane < nv) ? sc[lane] : -1e30f;
        float mx = s;
#pragma unroll
        for (int o = 16; o; o >>= 1) mx = fmaxf(mx, __shfl_xor_sync(0xffffffffu, mx, o));
        float e = (lane < nv) ? __expf(s - mx) : 0.0f;
        float sum = e;
#pragma unroll
        for (int o = 16; o; o >>= 1) sum += __shfl_xor_sync(0xffffffffu, sum, o);
        al[lane] = __fdividef(e, sum);
    }
    __syncthreads();
#pragma unroll
    for (int j = 0; j < 2; j++) {
        int h = tid + j * 256;
        float e = 0.0f;
        for (int mi = 0; mi < nv; mi++) {
            int slot = (t - 1 - mi) & 31;
            e = fmaf(al[mi], buf[((size_t)b * 32 + slot) * 512 + h], e);
        }
        he[(size_t)b * 1024 + 512 + h] = e;
    }
}

// ---------------- h update + logit ----------------
__global__ void __launch_bounds__(512) hout_k(
    const float* __restrict__ GP_t,
    const float* __restrict__ Wcls, const float* __restrict__ bcls,
    float* __restrict__ out, int t)
{
    int b = blockIdx.x, h = threadIdx.x;
    const float* hs = g_ws + OFF_HS;
    float pre = GP_t[(size_t)b * (TSEQ * HID) + h];
#pragma unroll
    for (int s = 0; s < 8; s++) pre += hs[(size_t)s * 65536 + (size_t)b * 512 + h];
    float ht = ftanh(pre);
    g_ws[OFF_H + (size_t)b * 512 + h] = ht;
    g_ws[OFF_BUF + ((size_t)b * 32 + (t & 31)) * 512 + h] = ht;

    float p = ht * Wcls[h];
#pragma unroll
    for (int o = 16; o; o >>= 1) p += __shfl_xor_sync(0xffffffffu, p, o);
    __shared__ float red[16];
    int wid = h >> 5, lane = h & 31;
    if (lane == 0) red[wid] = p;
    __syncthreads();
    if (wid == 0) {
        float p2 = (lane < 16) ? red[lane] : 0.0f;
#pragma unroll
        for (int o = 8; o; o >>= 1) p2 += __shfl_xor_sync(0xffffffffu, p2, o);
        if (lane == 0) out[(size_t)b * TSEQ + t] = p2 + bcls[0];
    }
}

// ---------------- host ----------------
extern "C" void kernel_launch(void* const* d_in, const int* in_sizes, int n_in,
                              void* d_out, int out_size)
{
    const float* x    = (const float*)d_in[0];
    const float* dlt  = (const float*)d_in[1];
    const float* gseq = (const float*)d_in[2];
    const float* Wsh  = (const float*)d_in[3];
    const float* Wsx  = (const float*)d_in[4];
    const float* Wst  = (const float*)d_in[5];
    const float* bs   = (const float*)d_in[6];
    const float* Wh5  = (const float*)d_in[7];
    const float* Wx5  = (const float*)d_in[8];
    const float* Ws5  = (const float*)d_in[9];
    const float* bg   = (const float*)d_in[10];
    const float* Waq  = (const float*)d_in[11];
    const float* Wah  = (const float*)d_in[12];
    const float* ba   = (const float*)d_in[13];
    const float* vt   = (const float*)d_in[14];
    const float* W_h  = (const float*)d_in[15];
    const float* W_e  = (const float*)d_in[16];
    const float* W_g  = (const float*)d_in[17];
    const float* b_h  = (const float*)d_in[18];
    const float* Wcls = (const float*)d_in[19];
    const float* bcls = (const float*)d_in[20];
    float* out = (float*)d_out;

    float* ws = nullptr;
    cudaGetSymbolAddress((void**)&ws, g_ws);

    // state init + weight packing
    zero_hc_k<<<512, 256>>>();
    packA_k<<<(512 * NA) / 256, 256>>>(Wsh, Wh5, Wah);
    packB_k<<<(512 * NB) / 256, 256>>>(Ws5);
    packD_k<<<(1024 * 512) / 256, 256>>>(W_h, W_e);
    packXG_k<<<(128 * NB) / 256, 256>>>(Wx5);

    // prologue GEMMs over all (b,t)
    // XS = x@W_sx + delta*W_st + b_s   [16384,512]
    gemm_k<2><<<dim3(16, 128, 1), 256>>>(x, DIN, Wsx, HID, DIN,
        ws + OFF_XS, HID, bs, Wst, dlt, nullptr, nullptr, nullptr);
    // XG = x@Wx + bg                    [16384,2560]
    gemm_k<1><<<dim3(80, 128, 1), 256>>>(x, DIN, ws + OFF_WXG, NB, DIN,
        ws + OFF_XG, NB, bg, nullptr, nullptr, nullptr, nullptr, nullptr);
    // GP = g@W_g + b_h                  [16384,512]
    gemm_k<1><<<dim3(16, 128, 1), 256>>>(gseq, DIN, W_g, HID, DIN,
        ws + OFF_GP, HID, b_h, nullptr, nullptr, nullptr, nullptr, nullptr);

    for (int t = 0; t < TSEQ; t++) {
        int slotp = (t + 31) & 31;  // slot of h_{t-1}
        // GEMM A: h_prev @ [W_sh | Wh*5 | Wah]; epilogue: s, preA, P-slot
        gemm_k<3><<<dim3(NA / 32, 1, 1), 256>>>(
            ws + OFF_H, HID, ws + OFF_WA, NA, HID,
            nullptr, 1,
            ws + OFF_XS + (size_t)t * HID, nullptr, nullptr,
            ws + OFF_S, ws + OFF_PREA, ws + OFF_P + (size_t)slotp * HID);
        // GEMM B: s @ Ws*5, split-K 2
        gemm_k<0><<<dim3(NB / 32, 1, 2), 256>>>(
            ws + OFF_S, HID, ws + OFF_WB, NB, HID / 2,
            ws + OFF_PREB, NB, nullptr, nullptr, nullptr, nullptr, nullptr, nullptr);
        // cell: gates, c, h_tilde
        cell_k<<<256, 256>>>(ws + OFF_XG + (size_t)t * NB, t);
        // GEMM C: [h_tilde|c] @ Waq, split-K 8
        gemm_k<0><<<dim3(HID / 32, 1, 8), 256>>>(
            ws + OFF_HC, 1024, Waq, HID, 1024 / 8,
            ws + OFF_QS, HID, nullptr, nullptr, nullptr, nullptr, nullptr, nullptr);
        // attention -> e_t
        attn_k<<<128, 256>>>(ba, vt, t);
        // GEMM D: [h_tilde|e] @ [W_h;W_e], split-K 8
        gemm_k<0><<<dim3(HID / 32, 1, 8), 256>>>(
            ws + OFF_HE, 1024, ws + OFF_WD, HID, 1024 / 8,
            ws + OFF_HS, HID, nullptr, nullptr, nullptr, nullptr, nullptr, nullptr);
        // h_t + buf append + logit
        hout_k<<<128, 512>>>(ws + OFF_GP + (size_t)t * HID, Wcls, bcls, out, t);
    }
    (void)in_sizes; (void)n_in; (void)out_size;
}

// round 4
// speedup vs baseline: 1.1740x; 1.1740x over previous
#include <cuda_runtime.h>
#include <math.h>

// ---------------- problem constants ----------------
#define BB   128   // batch
#define TSEQ 128   // sequence length
#define DIN  128   // input dim
#define HID  512   // hidden
#define MWIN 32    // attention window
#define NG   5     // gates

// packed widths
#define NA   3584  // [W_sh(512) | Wh*5(2560) | Wah(512)]
#define NB   2560  // Ws*5

// ---------------- workspace (single device global) ----------------
#define OFF_XS    0ull                                   // [B*T, 512]
#define SZ_XS     (16384ull*512ull)
#define OFF_XG    (OFF_XS + SZ_XS)                       // [B*T, 2560]
#define SZ_XG     (16384ull*2560ull)
#define OFF_GP    (OFF_XG + SZ_XG)                       // [B*T, 512]
#define SZ_GP     (16384ull*512ull)
#define OFF_WA    (OFF_GP + SZ_GP)                       // [512, 3584]
#define SZ_WA     (512ull*3584ull)
#define OFF_WB    (OFF_WA + SZ_WA)                       // [512, 2560]
#define SZ_WB     (512ull*2560ull)
#define OFF_WD    (OFF_WB + SZ_WB)                       // [1024, 512]
#define SZ_WD     (1024ull*512ull)
#define OFF_WXG   (OFF_WD + SZ_WD)                       // [128, 2560]
#define SZ_WXG    (128ull*2560ull)
#define OFF_PREA  (OFF_WXG + SZ_WXG)                     // [128, 2560]
#define SZ_PREA   (128ull*2560ull)
#define OFF_PREB  (OFF_PREA + SZ_PREA)                   // [2][128,2560]
#define SZ_PREB   (2ull*128ull*2560ull)
#define OFF_QS    (OFF_PREB + SZ_PREB)                   // [8][128,512]
#define SZ_QS     (8ull*128ull*512ull)
#define OFF_HS    (OFF_QS + SZ_QS)                       // [8][128,512]
#define SZ_HS     (8ull*128ull*512ull)
#define OFF_S     (OFF_HS + SZ_HS)                       // [128,512]
#define SZ_S      (128ull*512ull)
#define OFF_H     (OFF_S + SZ_S)                         // [128,512]
#define SZ_H      (128ull*512ull)
#define OFF_C     (OFF_H + SZ_H)                         // [128,512]
#define SZ_C      (128ull*512ull)
#define OFF_HC    (OFF_C + SZ_C)                         // [128,1024]  [h_tilde | c]
#define SZ_HC     (128ull*1024ull)
#define OFF_HE    (OFF_HC + SZ_HC)                       // [128,1024]  [h_tilde | e]
#define SZ_HE     (128ull*1024ull)
#define OFF_BUF   (OFF_HE + SZ_HE)                       // [128,32,512] circular h history
#define SZ_BUF    (128ull*32ull*512ull)
#define OFF_P     (OFF_BUF + SZ_BUF)                     // [128,32,512] projected history
#define SZ_P      (128ull*32ull*512ull)
#define WS_TOTAL  (OFF_P + SZ_P)

__device__ float g_ws[WS_TOTAL];

// ---------------- fast transcendentals ----------------
__device__ __forceinline__ float ftanh(float x) {
    float e = __expf(2.0f * x);
    return 1.0f - __fdividef(2.0f, e + 1.0f);
}
__device__ __forceinline__ float fsig(float x) {
    return __fdividef(1.0f, 1.0f + __expf(-x));
}

// ---------------- SIMT GEMM: C[64*gridDim.y, 32*gridDim.x] = A @ W ----------------
// Block tile 64 x 32, BK = 16, 128 threads, 4x4 per thread.
// Double-buffered smem with register prefetch: one __syncthreads per k-tile.
// split-K via blockIdx.z. EPI as in previous round.
#define GK 16
template<int EPI>
__global__ void __launch_bounds__(128) gemm_k(
    const float* __restrict__ A, int lda,
    const float* __restrict__ W, int ldw,
    int K,
    float* __restrict__ out, int ldo,
    const float* __restrict__ p1,
    const float* __restrict__ p2,
    const float* __restrict__ p3,
    float* __restrict__ q1,
    float* __restrict__ q2,
    float* __restrict__ q3)
{
    __shared__ float As[2][GK][64];
    __shared__ float Wsm[2][GK][32];

    const int tid = threadIdx.x;
    const int tx  = tid & 7;    // n quad (8 x 4 = 32 cols)
    const int ty  = tid >> 3;   // m quad (16 x 4 = 64 rows)
    const int n0  = blockIdx.x * 32;
    const int m0  = blockIdx.y * 64;
    const int z   = blockIdx.z;

    const float* Ab = A + (size_t)m0 * lda + (size_t)z * K;
    const float* Wb = W + (size_t)z * K * ldw + n0;

    // load-role indices
    const int am = tid >> 2;          // 0..31 (row; +32 for second half)
    const int ak = (tid & 3) << 2;    // k quad start: 0,4,8,12
    const int wk = tid >> 3;          // 0..15
    const int wn = (tid & 7) << 2;    // 0,4,..,28

    float acc[4][4];
#pragma unroll
    for (int r = 0; r < 4; r++)
#pragma unroll
        for (int c = 0; c < 4; c++) acc[r][c] = 0.0f;

    // prefetch k-tile 0
    float4 a0 = *reinterpret_cast<const float4*>(Ab + (size_t)am * lda + ak);
    float4 a1 = *reinterpret_cast<const float4*>(Ab + (size_t)(am + 32) * lda + ak);
    float4 w0 = *reinterpret_cast<const float4*>(Wb + (size_t)wk * ldw + wn);

    const int ntile = K / GK;
    for (int kt = 0; kt < ntile; kt++) {
        const int buf = kt & 1;
        // store prefetched regs into smem[buf]
        As[buf][ak + 0][am] = a0.x; As[buf][ak + 1][am] = a0.y;
        As[buf][ak + 2][am] = a0.z; As[buf][ak + 3][am] = a0.w;
        As[buf][ak + 0][am + 32] = a1.x; As[buf][ak + 1][am + 32] = a1.y;
        As[buf][ak + 2][am + 32] = a1.z; As[buf][ak + 3][am + 32] = a1.w;
        *reinterpret_cast<float4*>(&Wsm[buf][wk][wn]) = w0;
        __syncthreads();
        // prefetch next k-tile (latency overlapped with FMAs below)
        if (kt + 1 < ntile) {
            const float* Abn = Ab + (kt + 1) * GK;
            const float* Wbn = Wb + (size_t)(kt + 1) * GK * ldw;
            a0 = *reinterpret_cast<const float4*>(Abn + (size_t)am * lda + ak);
            a1 = *reinterpret_cast<const float4*>(Abn + (size_t)(am + 32) * lda + ak);
            w0 = *reinterpret_cast<const float4*>(Wbn + (size_t)wk * ldw + wn);
        }
#pragma unroll
        for (int k = 0; k < GK; k++) {
            float4 av = *reinterpret_cast<const float4*>(&As[buf][k][ty * 4]);
            float4 wv = *reinterpret_cast<const float4*>(&Wsm[buf][k][tx * 4]);
            float aa[4] = {av.x, av.y, av.z, av.w};
            float ww[4] = {wv.x, wv.y, wv.z, wv.w};
#pragma unroll
            for (int r = 0; r < 4; r++)
#pragma unroll
                for (int c = 0; c < 4; c++)
                    acc[r][c] = fmaf(aa[r], ww[c], acc[r][c]);
        }
    }

    // epilogue
    const size_t zoff = (size_t)z * gridDim.y * 64 * (EPI == 3 ? 0 : ldo);
#pragma unroll
    for (int r = 0; r < 4; r++) {
        int m = m0 + ty * 4 + r;
#pragma unroll
        for (int c = 0; c < 4; c++) {
            int n = n0 + tx * 4 + c;
            float v = acc[r][c];
            if (EPI == 0) {
                out[zoff + (size_t)m * ldo + n] = v;
            } else if (EPI == 1) {
                out[(size_t)m * ldo + n] = v + p1[n];
            } else if (EPI == 2) {
                out[(size_t)m * ldo + n] = v + p3[m] * p2[n] + p1[n];
            } else { // EPI == 3 : GEMM-A special
                if (n0 < 512) {
                    q1[(size_t)m * 512 + n] = ftanh(v + p1[(size_t)m * (TSEQ * HID) + n]);
                } else if (n0 < 3072) {
                    q2[(size_t)m * 2560 + (n - 512)] = v;
                } else {
                    q3[(size_t)m * (MWIN * HID) + (n - 3072)] = v;
                }
            }
        }
    }
}

// ---------------- pack kernels ----------------
__global__ void packA_k(const float* __restrict__ Wsh, const float* __restrict__ Wh,
                        const float* __restrict__ Wah)
{
    int idx = blockIdx.x * 256 + threadIdx.x;          // 512*3584
    int k = idx / NA, n = idx % NA;
    float v;
    if (n < 512) v = Wsh[k * 512 + n];
    else if (n < 3072) {
        int g = (n - 512) >> 9, h = (n - 512) & 511;
        v = Wh[(size_t)g * 262144 + k * 512 + h];
    } else v = Wah[k * 512 + (n - 3072)];
    g_ws[OFF_WA + idx] = v;
}
__global__ void packB_k(const float* __restrict__ Ws5)
{
    int idx = blockIdx.x * 256 + threadIdx.x;          // 512*2560
    int k = idx / NB, n = idx % NB;
    int g = n >> 9, h = n & 511;
    g_ws[OFF_WB + idx] = Ws5[(size_t)g * 262144 + k * 512 + h];
}
__global__ void packD_k(const float* __restrict__ W_h, const float* __restrict__ W_e)
{
    int idx = blockIdx.x * 256 + threadIdx.x;          // 1024*512
    int k = idx >> 9, n = idx & 511;
    g_ws[OFF_WD + idx] = (k < 512) ? W_h[k * 512 + n] : W_e[(k - 512) * 512 + n];
}
__global__ void packXG_k(const float* __restrict__ Wx5)
{
    int idx = blockIdx.x * 256 + threadIdx.x;          // 128*2560
    int d = idx / NB, n = idx % NB;
    int g = n >> 9, h = n & 511;
    g_ws[OFF_WXG + idx] = Wx5[(size_t)g * 65536 + d * 512 + h];
}
__global__ void zero_hc_k()
{
    int idx = blockIdx.x * 256 + threadIdx.x;          // 2*65536
    if (idx < 65536) g_ws[OFF_H + idx] = 0.0f;
    else             g_ws[OFF_C + (idx - 65536)] = 0.0f;
}

// ---------------- cell kernel ----------------
__global__ void __launch_bounds__(256) cell_k(const float* __restrict__ XG_t, int t)
{
    int idx = blockIdx.x * 256 + threadIdx.x;  // 0..65535
    int b = idx >> 9, h = idx & 511;
    const float* preA  = g_ws + OFF_PREA;
    const float* preB0 = g_ws + OFF_PREB;
    const float* preB1 = g_ws + OFF_PREB + 128ull * 2560ull;
    float pre[NG];
#pragma unroll
    for (int g = 0; g < NG; g++) {
        size_t col = (size_t)g * 512 + h;
        pre[g] = preA[(size_t)b * 2560 + col] + preB0[(size_t)b * 2560 + col]
               + preB1[(size_t)b * 2560 + col] + XG_t[(size_t)b * (TSEQ * 2560) + col];
    }
    float f  = fsig(pre[0]);
    float i_ = fsig(pre[1]);
    float Tt = fsig(pre[2]);
    float zt = ftanh(pre[3]);
    float o  = fsig(pre[4]);
    float sv = g_ws[OFF_S + idx];
    float cv = f * g_ws[OFF_C + idx] + i_ * zt + Tt * sv;
    g_ws[OFF_C + idx] = cv;
    float ht = o * ftanh(cv);
    g_ws[OFF_HC + (size_t)b * 1024 + h]       = ht;
    g_ws[OFF_HC + (size_t)b * 1024 + 512 + h] = cv;
    g_ws[OFF_HE + (size_t)b * 1024 + h]       = ht;
}

// ---------------- attention kernel (one block per batch row) ----------------
__global__ void __launch_bounds__(256) attn_k(
    const float* __restrict__ ba, const float* __restrict__ vt, int t)
{
    __shared__ float qv[512];
    __shared__ float sc[32];
    __shared__ float al[32];
    int b = blockIdx.x, tid = threadIdx.x;
    float* he = g_ws + OFF_HE;
    if (t == 0) {
        he[(size_t)b * 1024 + 512 + tid]       = 0.0f;
        he[(size_t)b * 1024 + 512 + 256 + tid] = 0.0f;
        return;
    }
    int nv = (t < MWIN) ? t : MWIN;
    const float* qs  = g_ws + OFF_QS;
    const float* P   = g_ws + OFF_P;
    const float* buf = g_ws + OFF_BUF;
#pragma unroll
    for (int j = 0; j < 2; j++) {
        int h = tid + j * 256;
        float q = ba[h];
#pragma unroll
        for (int s = 0; s < 8; s++) q += qs[(size_t)s * 65536 + (size_t)b * 512 + h];
        qv[h] = q;
    }
    __syncthreads();
    int wid = tid >> 5, lane = tid & 31;
    for (int mi = wid; mi < nv; mi += 8) {
        int slot = (t - 1 - mi) & 31;
        const float* Pp = P + ((size_t)b * 32 + slot) * 512;
        float ps = 0.0f;
        for (int h = lane; h < 512; h += 32)
            ps += vt[h] * ftanh(qv[h] + Pp[h]);
#pragma unroll
        for (int o = 16; o; o >>= 1) ps += __shfl_xor_sync(0xffffffffu, ps, o);
        if (lane == 0) sc[mi] = ps;
    }
    __syncthreads();
    if (wid == 0) {
        float s = (lane < nv) ? sc[lane] : -1e30f;
        float mx = s;
#pragma unroll
        for (int o = 16; o; o >>= 1) mx = fmaxf(mx, __shfl_xor_sync(0xffffffffu, mx, o));
        float e = (lane < nv) ? __expf(s - mx) : 0.0f;
        float sum = e;
#pragma unroll
        for (int o = 16; o; o >>= 1) sum += __shfl_xor_sync(0xffffffffu, sum, o);
        al[lane] = __fdividef(e, sum);
    }
    __syncthreads();
#pragma unroll
    for (int j = 0; j < 2; j++) {
        int h = tid + j * 256;
        float e = 0.0f;
        for (int mi = 0; mi < nv; mi++) {
            int slot = (t - 1 - mi) & 31;
            e = fmaf(al[mi], buf[((size_t)b * 32 + slot) * 512 + h], e);
        }
        he[(size_t)b * 1024 + 512 + h] = e;
    }
}

// ---------------- h update + logit ----------------
__global__ void __launch_bounds__(512) hout_k(
    const float* __restrict__ GP_t,
    const float* __restrict__ Wcls, const float* __restrict__ bcls,
    float* __restrict__ out, int t)
{
    int b = blockIdx.x, h = threadIdx.x;
    const float* hs = g_ws + OFF_HS;
    float pre = GP_t[(size_t)b * (TSEQ * HID) + h];
#pragma unroll
    for (int s = 0; s < 8; s++) pre += hs[(size_t)s * 65536 + (size_t)b * 512 + h];
    float ht = ftanh(pre);
    g_ws[OFF_H + (size_t)b * 512 + h] = ht;
    g_ws[OFF_BUF + ((size_t)b * 32 + (t & 31)) * 512 + h] = ht;

    float p = ht * Wcls[h];
#pragma unroll
    for (int o = 16; o; o >>= 1) p += __shfl_xor_sync(0xffffffffu, p, o);
    __shared__ float red[16];
    int wid = h >> 5, lane = h & 31;
    if (lane == 0) red[wid] = p;
    __syncthreads();
    if (wid == 0) {
        float p2 = (lane < 16) ? red[lane] : 0.0f;
#pragma unroll
        for (int o = 8; o; o >>= 1) p2 += __shfl_xor_sync(0xffffffffu, p2, o);
        if (lane == 0) out[(size_t)b * TSEQ + t] = p2 + bcls[0];
    }
}

// ---------------- host ----------------
extern "C" void kernel_launch(void* const* d_in, const int* in_sizes, int n_in,
                              void* d_out, int out_size)
{
    const float* x    = (const float*)d_in[0];
    const float* dlt  = (const float*)d_in[1];
    const float* gseq = (const float*)d_in[2];
    const float* Wsh  = (const float*)d_in[3];
    const float* Wsx  = (const float*)d_in[4];
    const float* Wst  = (const float*)d_in[5];
    const float* bs   = (const float*)d_in[6];
    const float* Wh5  = (const float*)d_in[7];
    const float* Wx5  = (const float*)d_in[8];
    const float* Ws5  = (const float*)d_in[9];
    const float* bg   = (const float*)d_in[10];
    const float* Waq  = (const float*)d_in[11];
    const float* Wah  = (const float*)d_in[12];
    const float* ba   = (const float*)d_in[13];
    const float* vt   = (const float*)d_in[14];
    const float* W_h  = (const float*)d_in[15];
    const float* W_e  = (const float*)d_in[16];
    const float* W_g  = (const float*)d_in[17];
    const float* b_h  = (const float*)d_in[18];
    const float* Wcls = (const float*)d_in[19];
    const float* bcls = (const float*)d_in[20];
    float* out = (float*)d_out;

    float* ws = nullptr;
    cudaGetSymbolAddress((void**)&ws, g_ws);

    // state init + weight packing
    zero_hc_k<<<512, 256>>>();
    packA_k<<<(512 * NA) / 256, 256>>>(Wsh, Wh5, Wah);
    packB_k<<<(512 * NB) / 256, 256>>>(Ws5);
    packD_k<<<(1024 * 512) / 256, 256>>>(W_h, W_e);
    packXG_k<<<(128 * NB) / 256, 256>>>(Wx5);

    // prologue GEMMs over all (b,t)   (64-row tiles -> grid.y = 16384/64 = 256)
    gemm_k<2><<<dim3(16, 256, 1), 128>>>(x, DIN, Wsx, HID, DIN,
        ws + OFF_XS, HID, bs, Wst, dlt, nullptr, nullptr, nullptr);
    gemm_k<1><<<dim3(80, 256, 1), 128>>>(x, DIN, ws + OFF_WXG, NB, DIN,
        ws + OFF_XG, NB, bg, nullptr, nullptr, nullptr, nullptr, nullptr);
    gemm_k<1><<<dim3(16, 256, 1), 128>>>(gseq, DIN, W_g, HID, DIN,
        ws + OFF_GP, HID, b_h, nullptr, nullptr, nullptr, nullptr, nullptr);

    for (int t = 0; t < TSEQ; t++) {
        int slotp = (t + 31) & 31;  // slot of h_{t-1}
        // GEMM A: h_prev @ [W_sh | Wh*5 | Wah]; 224 blocks
        gemm_k<3><<<dim3(NA / 32, 2, 1), 128>>>(
            ws + OFF_H, HID, ws + OFF_WA, NA, HID,
            nullptr, 1,
            ws + OFF_XS + (size_t)t * HID, nullptr, nullptr,
            ws + OFF_S, ws + OFF_PREA, ws + OFF_P + (size_t)slotp * HID);
        // GEMM B: s @ Ws*5, split-K 2; 320 blocks
        gemm_k<0><<<dim3(NB / 32, 2, 2), 128>>>(
            ws + OFF_S, HID, ws + OFF_WB, NB, HID / 2,
            ws + OFF_PREB, NB, nullptr, nullptr, nullptr, nullptr, nullptr, nullptr);
        // cell: gates, c, h_tilde
        cell_k<<<256, 256>>>(ws + OFF_XG + (size_t)t * NB, t);
        // GEMM C: [h_tilde|c] @ Waq, split-K 8; 256 blocks
        gemm_k<0><<<dim3(HID / 32, 2, 8), 128>>>(
            ws + OFF_HC, 1024, Waq, HID, 1024 / 8,
            ws + OFF_QS, HID, nullptr, nullptr, nullptr, nullptr, nullptr, nullptr);
        // attention -> e_t
        attn_k<<<128, 256>>>(ba, vt, t);
        // GEMM D: [h_tilde|e] @ [W_h;W_e], split-K 8; 256 blocks
        gemm_k<0><<<dim3(HID / 32, 2, 8), 128>>>(
            ws + OFF_HE, 1024, ws + OFF_WD, HID, 1024 / 8,
            ws + OFF_HS, HID, nullptr, nullptr, nullptr, nullptr, nullptr, nullptr);
        // h_t + buf append + logit
        hout_k<<<128, 512>>>(ws + OFF_GP + (size_t)t * HID, Wcls, bcls, out, t);
    }
    (void)in_sizes; (void)n_in; (void)out_size;
}

// round 5
// speedup vs baseline: 1.2948x; 1.1029x over previous
#include <cuda_runtime.h>
#include <math.h>

// ---------------- problem constants ----------------
#define BB   128
#define TSEQ 128
#define DIN  128
#define HID  512
#define MWIN 32
#define NG   5

#define NA   3584  // [W_sh(512) | Wh*5(2560) | Wah(512)]
#define NB   2560  // Ws*5

// ---------------- workspace ----------------
#define OFF_XS    0ull
#define SZ_XS     (16384ull*512ull)
#define OFF_XG    (OFF_XS + SZ_XS)
#define SZ_XG     (16384ull*2560ull)
#define OFF_GP    (OFF_XG + SZ_XG)
#define SZ_GP     (16384ull*512ull)
#define OFF_WA    (OFF_GP + SZ_GP)
#define SZ_WA     (512ull*3584ull)
#define OFF_WB    (OFF_WA + SZ_WA)
#define SZ_WB     (512ull*2560ull)
#define OFF_WD    (OFF_WB + SZ_WB)
#define SZ_WD     (1024ull*512ull)
#define OFF_WXG   (OFF_WD + SZ_WD)
#define SZ_WXG    (128ull*2560ull)
#define OFF_PREA  (OFF_WXG + SZ_WXG)
#define SZ_PREA   (128ull*2560ull)
#define OFF_PREB  (OFF_PREA + SZ_PREA)
#define SZ_PREB   (2ull*128ull*2560ull)
#define OFF_QS    (OFF_PREB + SZ_PREB)
#define SZ_QS     (8ull*128ull*512ull)
#define OFF_HS    (OFF_QS + SZ_QS)
#define SZ_HS     (8ull*128ull*512ull)
#define OFF_S     (OFF_HS + SZ_HS)
#define SZ_S      (128ull*512ull)
#define OFF_H     (OFF_S + SZ_S)
#define SZ_H      (128ull*512ull)
#define OFF_C     (OFF_H + SZ_H)
#define SZ_C      (128ull*512ull)
#define OFF_HC    (OFF_C + SZ_C)
#define SZ_HC     (128ull*1024ull)
#define OFF_HE    (OFF_HC + SZ_HC)
#define SZ_HE     (128ull*1024ull)
#define OFF_BUF   (OFF_HE + SZ_HE)
#define SZ_BUF    (128ull*32ull*512ull)
#define OFF_P     (OFF_BUF + SZ_BUF)
#define SZ_P      (128ull*32ull*512ull)
#define WS_TOTAL  (OFF_P + SZ_P)

__device__ float g_ws[WS_TOTAL];

// ---------------- fast transcendentals ----------------
__device__ __forceinline__ float ftanh(float x) {
    float e = __expf(2.0f * x);
    return 1.0f - __fdividef(2.0f, e + 1.0f);
}
__device__ __forceinline__ float fsig(float x) {
    return __fdividef(1.0f, 1.0f + __expf(-x));
}

// ---------------- f32x2 helpers ----------------
__device__ __forceinline__ unsigned long long pack2(float x, float y) {
    unsigned long long r;
    asm("mov.b64 %0, {%1, %2};" : "=l"(r) : "f"(x), "f"(y));
    return r;
}
__device__ __forceinline__ void ffma2(unsigned long long& d,
                                      unsigned long long a,
                                      unsigned long long b) {
    asm("fma.rn.f32x2 %0, %1, %2, %0;" : "+l"(d) : "l"(a), "l"(b));
}

// ---------------- FFMA2 GEMM: C[64*gy, 64*gx] = A @ W ----------------
// Block tile 64x64, BK=16, 256 threads, 4x4 per thread (8 f32x2 accs).
// Double-buffered smem + register prefetch; split-K via blockIdx.z.
// EPI: 0 raw (+z offset), 1 +bias[n], 2 +p3[m]*p2[n]+p1[n], 3 GEMM-A special.
#define GK 16
template<int EPI>
__global__ void __launch_bounds__(256) gemm_k(
    const float* __restrict__ A, int lda,
    const float* __restrict__ W, int ldw,
    int K,
    float* __restrict__ out, int ldo,
    const float* __restrict__ p1,
    const float* __restrict__ p2,
    const float* __restrict__ p3,
    float* __restrict__ q1,
    float* __restrict__ q2,
    float* __restrict__ q3)
{
    __shared__ float As[2][GK][64];
    __shared__ float Wsm[2][GK][64];

    const int tid = threadIdx.x;
    const int tx  = tid & 15;    // col quad (16 x 4 = 64)
    const int ty  = tid >> 4;    // row quad (16 x 4 = 64)
    const int n0  = blockIdx.x * 64;
    const int m0  = blockIdx.y * 64;
    const int z   = blockIdx.z;

    const float* Ab = A + (size_t)m0 * lda + (size_t)z * K;
    const float* Wb = W + (size_t)z * K * ldw + n0;

    // loader roles: one float4 each for A and W per k-tile
    const int am = tid >> 2;          // 0..63
    const int ak = (tid & 3) << 2;    // 0,4,8,12
    const int wk = tid >> 4;          // 0..15
    const int wn = (tid & 15) << 2;   // 0..60

    unsigned long long acc[4][2];
#pragma unroll
    for (int r = 0; r < 4; r++) { acc[r][0] = 0ull; acc[r][1] = 0ull; }

    // prefetch k-tile 0
    float4 a0 = *reinterpret_cast<const float4*>(Ab + (size_t)am * lda + ak);
    float4 w0 = *reinterpret_cast<const float4*>(Wb + (size_t)wk * ldw + wn);

    const int ntile = K / GK;
    for (int kt = 0; kt < ntile; kt++) {
        const int buf = kt & 1;
        As[buf][ak + 0][am] = a0.x; As[buf][ak + 1][am] = a0.y;
        As[buf][ak + 2][am] = a0.z; As[buf][ak + 3][am] = a0.w;
        *reinterpret_cast<float4*>(&Wsm[buf][wk][wn]) = w0;
        __syncthreads();
        if (kt + 1 < ntile) {
            const float* Abn = Ab + (kt + 1) * GK;
            const float* Wbn = Wb + (size_t)(kt + 1) * GK * ldw;
            a0 = *reinterpret_cast<const float4*>(Abn + (size_t)am * lda + ak);
            w0 = *reinterpret_cast<const float4*>(Wbn + (size_t)wk * ldw + wn);
        }
#pragma unroll
        for (int k = 0; k < GK; k++) {
            float4 av = *reinterpret_cast<const float4*>(&As[buf][k][ty * 4]);
            ulonglong2 wv = *reinterpret_cast<const ulonglong2*>(&Wsm[buf][k][tx * 4]);
            unsigned long long a2[4];
            a2[0] = pack2(av.x, av.x); a2[1] = pack2(av.y, av.y);
            a2[2] = pack2(av.z, av.z); a2[3] = pack2(av.w, av.w);
#pragma unroll
            for (int r = 0; r < 4; r++) {
                ffma2(acc[r][0], a2[r], wv.x);
                ffma2(acc[r][1], a2[r], wv.y);
            }
        }
    }

    // epilogue
    const size_t zoff = (size_t)z * gridDim.y * 64 * (EPI == 3 ? 0 : ldo);
#pragma unroll
    for (int r = 0; r < 4; r++) {
        int m = m0 + ty * 4 + r;
#pragma unroll
        for (int j = 0; j < 2; j++) {
            float2 vp = *reinterpret_cast<float2*>(&acc[r][j]);
#pragma unroll
            for (int half = 0; half < 2; half++) {
                int n = n0 + tx * 4 + j * 2 + half;
                float v = half ? vp.y : vp.x;
                if (EPI == 0) {
                    out[zoff + (size_t)m * ldo + n] = v;
                } else if (EPI == 1) {
                    out[(size_t)m * ldo + n] = v + p1[n];
                } else if (EPI == 2) {
                    out[(size_t)m * ldo + n] = v + p3[m] * p2[n] + p1[n];
                } else { // EPI == 3 : GEMM-A special
                    if (n0 < 512) {
                        q1[(size_t)m * 512 + n] = ftanh(v + p1[(size_t)m * (TSEQ * HID) + n]);
                    } else if (n0 < 3072) {
                        q2[(size_t)m * 2560 + (n - 512)] = v;
                    } else {
                        q3[(size_t)m * (MWIN * HID) + (n - 3072)] = v;
                    }
                }
            }
        }
    }
}

// ---------------- pack kernels ----------------
__global__ void packA_k(const float* __restrict__ Wsh, const float* __restrict__ Wh,
                        const float* __restrict__ Wah)
{
    int idx = blockIdx.x * 256 + threadIdx.x;          // 512*3584
    int k = idx / NA, n = idx % NA;
    float v;
    if (n < 512) v = Wsh[k * 512 + n];
    else if (n < 3072) {
        int g = (n - 512) >> 9, h = (n - 512) & 511;
        v = Wh[(size_t)g * 262144 + k * 512 + h];
    } else v = Wah[k * 512 + (n - 3072)];
    g_ws[OFF_WA + idx] = v;
}
__global__ void packB_k(const float* __restrict__ Ws5)
{
    int idx = blockIdx.x * 256 + threadIdx.x;          // 512*2560
    int k = idx / NB, n = idx % NB;
    int g = n >> 9, h = n & 511;
    g_ws[OFF_WB + idx] = Ws5[(size_t)g * 262144 + k * 512 + h];
}
__global__ void packD_k(const float* __restrict__ W_h, const float* __restrict__ W_e)
{
    int idx = blockIdx.x * 256 + threadIdx.x;          // 1024*512
    int k = idx >> 9, n = idx & 511;
    g_ws[OFF_WD + idx] = (k < 512) ? W_h[k * 512 + n] : W_e[(k - 512) * 512 + n];
}
__global__ void packXG_k(const float* __restrict__ Wx5)
{
    int idx = blockIdx.x * 256 + threadIdx.x;          // 128*2560
    int d = idx / NB, n = idx % NB;
    int g = n >> 9, h = n & 511;
    g_ws[OFF_WXG + idx] = Wx5[(size_t)g * 65536 + d * 512 + h];
}
__global__ void zero_hc_k()
{
    int idx = blockIdx.x * 256 + threadIdx.x;          // 2*65536
    if (idx < 65536) g_ws[OFF_H + idx] = 0.0f;
    else             g_ws[OFF_C + (idx - 65536)] = 0.0f;
}

// ---------------- cell kernel ----------------
__global__ void __launch_bounds__(256) cell_k(const float* __restrict__ XG_t, int t)
{
    int idx = blockIdx.x * 256 + threadIdx.x;  // 0..65535
    int b = idx >> 9, h = idx & 511;
    const float* preA  = g_ws + OFF_PREA;
    const float* preB0 = g_ws + OFF_PREB;
    const float* preB1 = g_ws + OFF_PREB + 128ull * 2560ull;
    float pre[NG];
#pragma unroll
    for (int g = 0; g < NG; g++) {
        size_t col = (size_t)g * 512 + h;
        pre[g] = preA[(size_t)b * 2560 + col] + preB0[(size_t)b * 2560 + col]
               + preB1[(size_t)b * 2560 + col] + XG_t[(size_t)b * (TSEQ * 2560) + col];
    }
    float f  = fsig(pre[0]);
    float i_ = fsig(pre[1]);
    float Tt = fsig(pre[2]);
    float zt = ftanh(pre[3]);
    float o  = fsig(pre[4]);
    float sv = g_ws[OFF_S + idx];
    float cv = f * g_ws[OFF_C + idx] + i_ * zt + Tt * sv;
    g_ws[OFF_C + idx] = cv;
    float ht = o * ftanh(cv);
    g_ws[OFF_HC + (size_t)b * 1024 + h]       = ht;
    g_ws[OFF_HC + (size_t)b * 1024 + 512 + h] = cv;
    g_ws[OFF_HE + (size_t)b * 1024 + h]       = ht;
}

// ---------------- attention kernel ----------------
__global__ void __launch_bounds__(256) attn_k(
    const float* __restrict__ ba, const float* __restrict__ vt, int t)
{
    __shared__ float qv[512];
    __shared__ float sc[32];
    __shared__ float al[32];
    int b = blockIdx.x, tid = threadIdx.x;
    float* he = g_ws + OFF_HE;
    if (t == 0) {
        he[(size_t)b * 1024 + 512 + tid]       = 0.0f;
        he[(size_t)b * 1024 + 512 + 256 + tid] = 0.0f;
        return;
    }
    int nv = (t < MWIN) ? t : MWIN;
    const float* qs  = g_ws + OFF_QS;
    const float* P   = g_ws + OFF_P;
    const float* buf = g_ws + OFF_BUF;
#pragma unroll
    for (int j = 0; j < 2; j++) {
        int h = tid + j * 256;
        float q = ba[h];
#pragma unroll
        for (int s = 0; s < 8; s++) q += qs[(size_t)s * 65536 + (size_t)b * 512 + h];
        qv[h] = q;
    }
    __syncthreads();
    int wid = tid >> 5, lane = tid & 31;
    for (int mi = wid; mi < nv; mi += 8) {
        int slot = (t - 1 - mi) & 31;
        const float* Pp = P + ((size_t)b * 32 + slot) * 512;
        float ps = 0.0f;
        for (int h = lane; h < 512; h += 32)
            ps += vt[h] * ftanh(qv[h] + Pp[h]);
#pragma unroll
        for (int o = 16; o; o >>= 1) ps += __shfl_xor_sync(0xffffffffu, ps, o);
        if (lane == 0) sc[mi] = ps;
    }
    __syncthreads();
    if (wid == 0) {
        float s = (lane < nv) ? sc[lane] : -1e30f;
        float mx = s;
#pragma unroll
        for (int o = 16; o; o >>= 1) mx = fmaxf(mx, __shfl_xor_sync(0xffffffffu, mx, o));
        float e = (lane < nv) ? __expf(s - mx) : 0.0f;
        float sum = e;
#pragma unroll
        for (int o = 16; o; o >>= 1) sum += __shfl_xor_sync(0xffffffffu, sum, o);
        al[lane] = __fdividef(e, sum);
    }
    __syncthreads();
#pragma unroll
    for (int j = 0; j < 2; j++) {
        int h = tid + j * 256;
        float e = 0.0f;
        for (int mi = 0; mi < nv; mi++) {
            int slot = (t - 1 - mi) & 31;
            e = fmaf(al[mi], buf[((size_t)b * 32 + slot) * 512 + h], e);
        }
        he[(size_t)b * 1024 + 512 + h] = e;
    }
}

// ---------------- h update + logit ----------------
__global__ void __launch_bounds__(512) hout_k(
    const float* __restrict__ GP_t,
    const float* __restrict__ Wcls, const float* __restrict__ bcls,
    float* __restrict__ out, int t)
{
    int b = blockIdx.x, h = threadIdx.x;
    const float* hs = g_ws + OFF_HS;
    float pre = GP_t[(size_t)b * (TSEQ * HID) + h];
#pragma unroll
    for (int s = 0; s < 8; s++) pre += hs[(size_t)s * 65536 + (size_t)b * 512 + h];
    float ht = ftanh(pre);
    g_ws[OFF_H + (size_t)b * 512 + h] = ht;
    g_ws[OFF_BUF + ((size_t)b * 32 + (t & 31)) * 512 + h] = ht;

    float p = ht * Wcls[h];
#pragma unroll
    for (int o = 16; o; o >>= 1) p += __shfl_xor_sync(0xffffffffu, p, o);
    __shared__ float red[16];
    int wid = h >> 5, lane = h & 31;
    if (lane == 0) red[wid] = p;
    __syncthreads();
    if (wid == 0) {
        float p2 = (lane < 16) ? red[lane] : 0.0f;
#pragma unroll
        for (int o = 8; o; o >>= 1) p2 += __shfl_xor_sync(0xffffffffu, p2, o);
        if (lane == 0) out[(size_t)b * TSEQ + t] = p2 + bcls[0];
    }
}

// ---------------- host ----------------
extern "C" void kernel_launch(void* const* d_in, const int* in_sizes, int n_in,
                              void* d_out, int out_size)
{
    const float* x    = (const float*)d_in[0];
    const float* dlt  = (const float*)d_in[1];
    const float* gseq = (const float*)d_in[2];
    const float* Wsh  = (const float*)d_in[3];
    const float* Wsx  = (const float*)d_in[4];
    const float* Wst  = (const float*)d_in[5];
    const float* bs   = (const float*)d_in[6];
    const float* Wh5  = (const float*)d_in[7];
    const float* Wx5  = (const float*)d_in[8];
    const float* Ws5  = (const float*)d_in[9];
    const float* bg   = (const float*)d_in[10];
    const float* Waq  = (const float*)d_in[11];
    const float* Wah  = (const float*)d_in[12];
    const float* ba   = (const float*)d_in[13];
    const float* vt   = (const float*)d_in[14];
    const float* W_h  = (const float*)d_in[15];
    const float* W_e  = (const float*)d_in[16];
    const float* W_g  = (const float*)d_in[17];
    const float* b_h  = (const float*)d_in[18];
    const float* Wcls = (const float*)d_in[19];
    const float* bcls = (const float*)d_in[20];
    float* out = (float*)d_out;

    float* ws = nullptr;
    cudaGetSymbolAddress((void**)&ws, g_ws);

    zero_hc_k<<<512, 256>>>();
    packA_k<<<(512 * NA) / 256, 256>>>(Wsh, Wh5, Wah);
    packB_k<<<(512 * NB) / 256, 256>>>(Ws5);
    packD_k<<<(1024 * 512) / 256, 256>>>(W_h, W_e);
    packXG_k<<<(128 * NB) / 256, 256>>>(Wx5);

    // prologue GEMMs (64x64 tiles; grid.y = 16384/64 = 256)
    gemm_k<2><<<dim3(8, 256, 1), 256>>>(x, DIN, Wsx, HID, DIN,
        ws + OFF_XS, HID, bs, Wst, dlt, nullptr, nullptr, nullptr);
    gemm_k<1><<<dim3(40, 256, 1), 256>>>(x, DIN, ws + OFF_WXG, NB, DIN,
        ws + OFF_XG, NB, bg, nullptr, nullptr, nullptr, nullptr, nullptr);
    gemm_k<1><<<dim3(8, 256, 1), 256>>>(gseq, DIN, W_g, HID, DIN,
        ws + OFF_GP, HID, b_h, nullptr, nullptr, nullptr, nullptr, nullptr);

    for (int t = 0; t < TSEQ; t++) {
        int slotp = (t + 31) & 31;  // slot of h_{t-1}
        // GEMM A: h_prev @ [W_sh | Wh*5 | Wah]; 112 blocks
        gemm_k<3><<<dim3(NA / 64, 2, 1), 256>>>(
            ws + OFF_H, HID, ws + OFF_WA, NA, HID,
            nullptr, 1,
            ws + OFF_XS + (size_t)t * HID, nullptr, nullptr,
            ws + OFF_S, ws + OFF_PREA, ws + OFF_P + (size_t)slotp * HID);
        // GEMM B: s @ Ws*5, split-K 2; 160 blocks
        gemm_k<0><<<dim3(NB / 64, 2, 2), 256>>>(
            ws + OFF_S, HID, ws + OFF_WB, NB, HID / 2,
            ws + OFF_PREB, NB, nullptr, nullptr, nullptr, nullptr, nullptr, nullptr);
        // cell: gates, c, h_tilde
        cell_k<<<256, 256>>>(ws + OFF_XG + (size_t)t * NB, t);
        // GEMM C: [h_tilde|c] @ Waq, split-K 8; 128 blocks
        gemm_k<0><<<dim3(HID / 64, 2, 8), 256>>>(
            ws + OFF_HC, 1024, Waq, HID, 1024 / 8,
            ws + OFF_QS, HID, nullptr, nullptr, nullptr, nullptr, nullptr, nullptr);
        // attention -> e_t
        attn_k<<<128, 256>>>(ba, vt, t);
        // GEMM D: [h_tilde|e] @ [W_h;W_e], split-K 8; 128 blocks
        gemm_k<0><<<dim3(HID / 64, 2, 8), 256>>>(
            ws + OFF_HE, 1024, ws + OFF_WD, HID, 1024 / 8,
            ws + OFF_HS, HID, nullptr, nullptr, nullptr, nullptr, nullptr, nullptr);
        // h_t + buf append + logit
        hout_k<<<128, 512>>>(ws + OFF_GP + (size_t)t * HID, Wcls, bcls, out, t);
    }
    (void)in_sizes; (void)n_in; (void)out_size;
}